// round 17
// baseline (speedup 1.0000x reference)
#include <cuda_runtime.h>
#include <math.h>

constexpr int FH   = 96;
constexpr int FW   = 96;
constexpr int FC   = 512;
constexpr int FB   = 16;
constexpr int NROI = 32;
constexpr int NREG = 50;          // 1 + 4 + 9 + 36
constexpr int C4   = FC / 4;      // 128 float4 channels
constexpr int RS   = FW * C4;     // row stride in float4 units
constexpr int CH   = 8;           // rows per chunk
constexpr int NCK  = FH / CH;     // 12
constexpr int YBIG = 1 << 30;

__device__ int4 d_regions[NROI * NREG];

// ---------------------------------------------------------------------------
// Prep: init ALL 50 regions to -inf bits + exact Python-double boundaries
// (verified math, unchanged since R1).
// ---------------------------------------------------------------------------
__global__ void prep_kernel(const int* __restrict__ rois,
                            unsigned int* __restrict__ out) {
    int gid = blockIdx.x * blockDim.x + threadIdx.x;

    if (gid < FB * NROI * NREG * 128) {
        ((uint4*)out)[gid] =
            make_uint4(0xFF800000u, 0xFF800000u, 0xFF800000u, 0xFF800000u);
    }

    if (gid >= NROI * NREG) return;
    int roi = gid / NREG;
    int k   = gid % NREG;

    int P, off;
    if      (k < 1)  { P = 1; off = 0; }
    else if (k < 5)  { P = 2; off = 1; }
    else if (k < 14) { P = 3; off = 5; }
    else             { P = 6; off = 14; }
    int idx = k - off;
    int ix  = idx / P;
    int jy  = idx % P;

    double x = (double)rois[roi * 4 + 0];
    double y = (double)rois[roi * 4 + 1];
    double w = (double)rois[roi * 4 + 2];
    double h = (double)rois[roi * 4 + 3];

    double cl = h / (double)P;   // x-axis step (reference quirk)
    double rl = w / (double)P;   // y-axis step

    double tx = __dadd_rn(x, __dmul_rn((double)ix, cl));
    int x1 = (int)rint(tx);
    int x2 = (int)rint(__dadd_rn(tx, cl));

    double ty = __dadd_rn(y, __dmul_rn((double)jy, rl));
    int y1 = (int)rint(ty);
    int y2 = (int)rint(__dadd_rn(ty, rl));

    x1 = max(0, min(FW, x1));
    x2 = max(0, min(FW, x2));
    y1 = max(0, min(FH, y1));
    y2 = max(0, min(FH, y2));

    d_regions[roi * NREG + k] = make_int4(x1, x2, y1, y2);
}

// Sign-split float atomic max on raw bits (proven rel_err=0 in R6-R16).
__device__ __forceinline__ void atomicMaxFloat(float* addr, float v) {
    if (v >= 0.0f) atomicMax((int*)addr, __float_as_int(v));
    else           atomicMin((unsigned int*)addr, __float_as_uint(v));
}

__device__ __forceinline__ void vmax4(float4& a, const float4 b) {
    a.x = fmaxf(a.x, b.x);
    a.y = fmaxf(a.y, b.y);
    a.z = fmaxf(a.z, b.z);
    a.w = fmaxf(a.w, b.w);
}

__device__ __forceinline__ void atomic4(float* o, const float4 a) {
    atomicMaxFloat(o + 0, a.x);
    atomicMaxFloat(o + 1, a.y);
    atomicMaxFloat(o + 2, a.z);
    atomicMaxFloat(o + 3, a.w);
}

#define NEG4 make_float4(-INFINITY, -INFINITY, -INFINITY, -INFINITY)

// ---------------------------------------------------------------------------
// Multi-row segment scans, tree-combined into t (max is associative/
// commutative -> combine order irrelevant, bit-exact).
// NR=1/2: x-unroll 2 (rare short-run paths, unchanged from R16).
// NR=4 wide path: x-unroll 3 -> 12 independent LDG.128 in flight.
// ---------------------------------------------------------------------------
template <int NR>
__device__ __forceinline__ void scanR(const float4* __restrict__ rp,
                                      int xa, int xb, float4& t) {
    int x = xa;
    for (; x + 2 <= xb; x += 2) {
        const float4* p0 = rp + (size_t)x * C4;
        const float4* p1 = p0 + C4;
        float4 a = __ldg(p0);
        float4 b = __ldg(p1);
        if (NR > 1) {
            float4 c = __ldg(p0 + RS);
            float4 d = __ldg(p1 + RS);
            if (NR > 2) {
                float4 e = __ldg(p0 + 2 * RS);
                float4 f = __ldg(p1 + 2 * RS);
                float4 g = __ldg(p0 + 3 * RS);
                float4 h = __ldg(p1 + 3 * RS);
                vmax4(a, e); vmax4(b, f); vmax4(c, g); vmax4(d, h);
            }
            vmax4(a, c); vmax4(b, d);
        }
        vmax4(a, b);
        vmax4(t, a);
    }
    if (x < xb) {
        const float4* p0 = rp + (size_t)x * C4;
        float4 a = __ldg(p0);
        if (NR > 1) {
            float4 c = __ldg(p0 + RS);
            if (NR > 2) {
                float4 e = __ldg(p0 + 2 * RS);
                float4 g = __ldg(p0 + 3 * RS);
                vmax4(a, e); vmax4(c, g);
            }
            vmax4(a, c);
        }
        vmax4(t, a);
    }
}

// 4-row, x-unroll-3 wide scan: 12 loads in flight.
__device__ __forceinline__ void scanR4w(const float4* __restrict__ rp,
                                        int xa, int xb, float4& t) {
    int x = xa;
    for (; x + 3 <= xb; x += 3) {
        const float4* p0 = rp + (size_t)x * C4;
        const float4* p1 = p0 + C4;
        const float4* p2 = p1 + C4;
        float4 a0 = __ldg(p0);
        float4 a1 = __ldg(p0 + RS);
        float4 a2 = __ldg(p0 + 2 * RS);
        float4 a3 = __ldg(p0 + 3 * RS);
        float4 b0 = __ldg(p1);
        float4 b1 = __ldg(p1 + RS);
        float4 b2 = __ldg(p1 + 2 * RS);
        float4 b3 = __ldg(p1 + 3 * RS);
        float4 c0 = __ldg(p2);
        float4 c1 = __ldg(p2 + RS);
        float4 c2 = __ldg(p2 + 2 * RS);
        float4 c3 = __ldg(p2 + 3 * RS);
        vmax4(a0, a1); vmax4(a2, a3); vmax4(a0, a2);
        vmax4(b0, b1); vmax4(b2, b3); vmax4(b0, b2);
        vmax4(c0, c1); vmax4(c2, c3); vmax4(c0, c2);
        vmax4(a0, b0); vmax4(a0, c0);
        vmax4(t, a0);
    }
    if (x + 2 <= xb) {
        const float4* p0 = rp + (size_t)x * C4;
        const float4* p1 = p0 + C4;
        float4 a0 = __ldg(p0);
        float4 a1 = __ldg(p0 + RS);
        float4 a2 = __ldg(p0 + 2 * RS);
        float4 a3 = __ldg(p0 + 3 * RS);
        float4 b0 = __ldg(p1);
        float4 b1 = __ldg(p1 + RS);
        float4 b2 = __ldg(p1 + 2 * RS);
        float4 b3 = __ldg(p1 + 3 * RS);
        vmax4(a0, a1); vmax4(a2, a3);
        vmax4(b0, b1); vmax4(b2, b3);
        vmax4(a0, a2); vmax4(b0, b2);
        vmax4(a0, b0);
        vmax4(t, a0);
        x += 2;
    }
    if (x < xb) {
        const float4* p0 = rp + (size_t)x * C4;
        float4 a0 = __ldg(p0);
        float4 a1 = __ldg(p0 + RS);
        float4 a2 = __ldg(p0 + 2 * RS);
        float4 a3 = __ldg(p0 + 3 * RS);
        vmax4(a0, a1); vmax4(a2, a3); vmax4(a0, a2);
        vmax4(t, a0);
    }
}

// NR dispatch (NR=4 -> wide path)
template <int NR>
__device__ __forceinline__ void scanD(const float4* __restrict__ rp,
                                      int xa, int xb, float4& t) {
    if (NR == 4) scanR4w(rp, xa, xb, t);
    else         scanR<NR>(rp, xa, xb, t);
}

// Run body: same exact segment/gap/overlap coverage as PASSING R14-R16,
// per-segment deferred merge into the 1-3 target accumulators.
#define SEG(NR, xa, xb, ...) do {                                             \
        float4 t = NEG4;                                                      \
        scanD<NR>(rp0, (xa), (xb), t);                                        \
        __VA_ARGS__;                                                          \
    } while (0)

#define RUN_BODY(NR) do {                                                     \
    if (in6) {                                                                \
        SEG(NR, s6[0], e6[0],        vmax4(a6[0],t); vmax4(a3[0],t); vmax4(a2[0],t)); \
        SEG(NR, s6[1], e6[1],        vmax4(a6[1],t); vmax4(a3[0],t); vmax4(a2[0],t)); \
        SEG(NR, s6[2], min(e6[2],m), vmax4(a6[2],t); vmax4(a3[1],t); vmax4(a2[0],t)); \
        SEG(NR, max(s6[2],m), e6[2], vmax4(a6[2],t); vmax4(a3[1],t); vmax4(a2[1],t)); \
        if (e6[2] < s6[3]) {                                                  \
            SEG(NR, e6[2], min(s6[3],m), vmax4(a3[1],t); vmax4(a2[0],t));     \
            SEG(NR, max(e6[2],m), s6[3], vmax4(a3[1],t); vmax4(a2[1],t));     \
        }                                                                     \
        SEG(NR, s6[3], min(e6[3],m), vmax4(a6[3],t); vmax4(a3[1],t); vmax4(a2[0],t)); \
        SEG(NR, max(s6[3],m), e6[3], vmax4(a6[3],t); vmax4(a3[1],t); vmax4(a2[1],t)); \
        SEG(NR, s6[4], e6[4],        vmax4(a6[4],t); vmax4(a3[2],t); vmax4(a2[1],t)); \
        SEG(NR, s6[5], e6[5],        vmax4(a6[5],t); vmax4(a3[2],t); vmax4(a2[1],t)); \
        if (ov) {                                                             \
            _Pragma("unroll")                                                 \
            for (int i = 0; i < 6; i++) {                                     \
                float4 t2 = NEG4;                                             \
                scanD<NR>(rp0, s6[i], e6[i], t2);                             \
                atomic4(outb + ((size_t)(14 + i * 6 + jb6 + 1) << 9), t2);    \
            }                                                                 \
        }                                                                     \
    } else {                                                                  \
        SEG(NR, s3[0], e3[0],        vmax4(a3[0],t); vmax4(a2[0],t));         \
        SEG(NR, s3[1], min(e3[1],m), vmax4(a3[1],t); vmax4(a2[0],t));         \
        SEG(NR, max(s3[1],m), e3[1], vmax4(a3[1],t); vmax4(a2[1],t));         \
        SEG(NR, s3[2], e3[2],        vmax4(a3[2],t); vmax4(a2[1],t));         \
    }                                                                         \
} while (0)

// ---------------------------------------------------------------------------
// SINGLE-SWEEP kernel (R14-R16 algorithm) + run-length multi-row dispatch.
// ---------------------------------------------------------------------------
__global__ void __launch_bounds__(128)
roi_pool_onesweep(const float* __restrict__ fm, float* __restrict__ out) {
    int bid = blockIdx.x;
    int ck  = bid % NCK;
    int rr  = bid / NCK;
    int roi = rr & 31;
    int b   = rr >> 5;            // batch slowest: co-resident blocks share image
    int c   = threadIdx.x;

    const int4* regs = d_regions + roi * NREG;
    int4 r0 = __ldg(&regs[0]);    // pool1 box = union box, exact
    int row_lo = max(r0.z, ck * CH);
    int row_hi = min(r0.w, ck * CH + CH);
    if (row_lo >= row_hi) return;

    int s6[6], e6[6];
#pragma unroll
    for (int i = 0; i < 6; i++) { int4 q = __ldg(&regs[14 + i * 6]); s6[i] = q.x; e6[i] = q.y; }
    int s3[3], e3[3];
#pragma unroll
    for (int i = 0; i < 3; i++) { int4 q = __ldg(&regs[5 + i * 3]);  s3[i] = q.x; e3[i] = q.y; }
    int m  = __ldg(&regs[3]).x;   // pool2 x-cut  (exact)
    int ym = __ldg(&regs[2]).z;   // pool2 y-cut  (exact)

    const float4* fmb  = (const float4*)fm + (size_t)b * FH * FW * C4 + c;
    float*        outb = out + (((size_t)(b * NROI + roi) * NREG) << 9) + c * 4;

    float4 a6[6], a3[3], a2[2];
#pragma unroll
    for (int i = 0; i < 6; i++) a6[i] = NEG4;
#pragma unroll
    for (int i = 0; i < 3; i++) a3[i] = NEG4;
    a2[0] = NEG4; a2[1] = NEG4;

    // pool6 band walker (only the 2|3 seam can gap/overlap; verified)
    int jb6 = 0, b6y1, b6y2, b6y1n;
    { int4 q = __ldg(&regs[14]); b6y1 = q.z; b6y2 = q.w; }
    while (jb6 < 6 && row_lo >= b6y2) {
        jb6++;
        if (jb6 < 6) { int4 q = __ldg(&regs[14 + jb6]); b6y1 = q.z; b6y2 = q.w; }
    }
    b6y1n = (jb6 + 1 < 6) ? __ldg(&regs[14 + jb6 + 1]).z : YBIG;
    if (jb6 >= 6) { b6y1 = YBIG; b6y2 = YBIG; b6y1n = YBIG; }

    // pool3 band walker (tiles exactly; verified rel_err=0)
    int jb3 = 0, b3y2 = __ldg(&regs[5]).w;
    while (jb3 < 3 && row_lo >= b3y2) {
        jb3++;
        b3y2 = (jb3 < 3) ? __ldg(&regs[5 + jb3]).w : YBIG;
    }

    int b2cur = (row_lo >= ym) ? 1 : 0;

    for (int y = row_lo; y < row_hi; ) {
        // walkers: flush-on-advance (NEG flushes harmless)
        while (jb6 < 6 && y >= b6y2) {
#pragma unroll
            for (int i = 0; i < 6; i++) {
                atomic4(outb + ((size_t)(14 + i * 6 + jb6) << 9), a6[i]);
                a6[i] = NEG4;
            }
            jb6++;
            if (jb6 < 6) {
                int4 q = __ldg(&regs[14 + jb6]); b6y1 = q.z; b6y2 = q.w;
                b6y1n = (jb6 + 1 < 6) ? __ldg(&regs[14 + jb6 + 1]).z : YBIG;
            } else { b6y1 = YBIG; b6y2 = YBIG; b6y1n = YBIG; }
        }
        while (jb3 < 3 && y >= b3y2) {
#pragma unroll
            for (int i = 0; i < 3; i++) {
                atomic4(outb + ((size_t)(5 + i * 3 + jb3) << 9), a3[i]);
                a3[i] = NEG4;
            }
            jb3++;
            b3y2 = (jb3 < 3) ? __ldg(&regs[5 + jb3]).w : YBIG;
        }
        if (b2cur == 0 && y >= ym) {
#pragma unroll
            for (int i = 0; i < 2; i++) {
                atomic4(outb + ((size_t)(1 + i * 2) << 9), a2[i]);
                atomic4(outb, a2[i]);                 // pool1 fold
                a2[i] = NEG4;
            }
            b2cur = 1;
        }

        // run of rows with constant band state
        int ynext = min(min(row_hi, b6y2), b3y2);
        if (y < ym)    ynext = min(ynext, ym);
        if (y < b6y1)  ynext = min(ynext, b6y1);
        if (y < b6y1n) ynext = min(ynext, b6y1n);

        bool in6 = (y >= b6y1);
        bool ov  = (y >= b6y1n);
        const float4* rp0 = fmb + (size_t)y * RS;
        int L = ynext - y;

        if (L >= 4)      { RUN_BODY(4); y += 4; }
        else if (L >= 2) { RUN_BODY(2); y += 2; }
        else             { RUN_BODY(1); y += 1; }
    }

    // final flushes (NEG-safe)
    if (jb6 < 6) {
#pragma unroll
        for (int i = 0; i < 6; i++)
            atomic4(outb + ((size_t)(14 + i * 6 + jb6) << 9), a6[i]);
    }
    if (jb3 < 3) {
#pragma unroll
        for (int i = 0; i < 3; i++)
            atomic4(outb + ((size_t)(5 + i * 3 + jb3) << 9), a3[i]);
    }
#pragma unroll
    for (int i = 0; i < 2; i++) {
        atomic4(outb + ((size_t)(1 + i * 2 + b2cur) << 9), a2[i]);
        atomic4(outb, a2[i]);                         // pool1 fold
    }
}

extern "C" void kernel_launch(void* const* d_in, const int* in_sizes, int n_in,
                              void* d_out, int out_size) {
    const float* fm   = (const float*)d_in[0];
    const int*   rois = (const int*)d_in[1];
    float*       out  = (float*)d_out;

    int n4 = out_size / 4;                            // whole output as uint4
    prep_kernel<<<(n4 + 255) / 256, 256>>>(rois, (unsigned int*)out);
    roi_pool_onesweep<<<FB * NROI * NCK, 128>>>(fm, out);
}